// round 14
// baseline (speedup 1.0000x reference)
#include <cuda_runtime.h>
#include <cuda_fp16.h>
#include <cstdint>

#define NUM_USERS 100000
#define NUM_ITEMS 50000
#define N_NODES   150000
#define C         64
#define NNZ       2400000
#define BATCH     8192
#define NEG_SLOPE 0.1f
#define EPS       1e-12f

#define BSHIFT 7
#define NB ((N_NODES + 127) >> 7)   // 1172 buckets of 128 cols

// Normalized layer outputs p0,p1,p2 in fp16 (gather/score sources).
__device__ __half g_h[3][(size_t)N_NODES * C];
// fp16 RED accumulation targets. Layer1->rawA, 2->rawB, 3->rawA.
__device__ __half g_rawA[(size_t)N_NODES * C];
__device__ __half g_rawB[(size_t)N_NODES * C];
// Rows where layer-3 output is actually consumed (batch rows).
__device__ unsigned char g_needed[N_NODES];
// Column-bucket-sorted edge arrays (built once, reused by all layers).
__device__ int  g_bcnt[NB];
__device__ int  g_bcur[NB];
__device__ int  g_scol[NNZ];
__device__ int2 g_srv[NNZ];          // {row, float_bits(val)}
// Compacted layer-3 edges (subset of sorted — stays col-ordered).
__device__ int  g_cc[NNZ];
__device__ int2 g_crv[NNZ];
__device__ int  g_count;

__device__ __forceinline__ float lrelu(float x) {
    return x >= 0.0f ? x : NEG_SLOPE * x;
}

__device__ __forceinline__ float warp_sum(float s) {
#pragma unroll
    for (int o = 16; o; o >>= 1) s += __shfl_xor_sync(0xffffffffu, s, o);
    return s;
}

__device__ __forceinline__ float seg16_sum(float s) {
#pragma unroll
    for (int o = 8; o; o >>= 1) s += __shfl_xor_sync(0xffffffffu, s, o);
    return s;
}

// ---------------- prologue zeroing ----------------
__global__ __launch_bounds__(256) void k_zero_pro() {
    int i = blockIdx.x * blockDim.x + threadIdx.x;
    if (i == 0) g_count = 0;
    if (i < NB) g_bcnt[i] = 0;
    if (i * 4 < N_NODES)
        reinterpret_cast<unsigned int*>(g_needed)[i] = 0u;
}

__global__ __launch_bounds__(256) void k_mark(const int* __restrict__ users,
                                              const int* __restrict__ adj,
                                              const int* __restrict__ weak,
                                              const int* __restrict__ strong) {
    int i = blockIdx.x * blockDim.x + threadIdx.x;
    if (i >= BATCH) return;
    g_needed[users[i]] = 1;
    g_needed[NUM_USERS + adj[i]] = 1;
    g_needed[NUM_USERS + weak[i]] = 1;
    g_needed[NUM_USERS + strong[i]] = 1;
}

// ---------------- bucket histogram (smem-aggregated) ----------------
__global__ __launch_bounds__(256) void k_bhist(const int* __restrict__ ecol) {
    __shared__ int sh[NB];
    for (int i = threadIdx.x; i < NB; i += 256) sh[i] = 0;
    __syncthreads();
    int stride = gridDim.x * blockDim.x;
    for (int e = blockIdx.x * blockDim.x + threadIdx.x; e < NNZ; e += stride)
        atomicAdd(&sh[__ldg(ecol + e) >> BSHIFT], 1);
    __syncthreads();
    for (int i = threadIdx.x; i < NB; i += 256)
        if (sh[i]) atomicAdd(&g_bcnt[i], sh[i]);
}

// ---------------- exclusive scan over NB buckets -> cursors ----------------
__global__ __launch_bounds__(1024) void k_bscan() {
    __shared__ int sums[1024];
    int t = threadIdx.x;
    int i0 = t * 2, i1 = t * 2 + 1;
    int a0 = (i0 < NB) ? g_bcnt[i0] : 0;
    int a1 = (i1 < NB) ? g_bcnt[i1] : 0;
    sums[t] = a0 + a1;
    __syncthreads();
#pragma unroll
    for (int off = 1; off < 1024; off <<= 1) {
        int v = (t >= off) ? sums[t - off] : 0;
        __syncthreads();
        sums[t] += v;
        __syncthreads();
    }
    int base = (t > 0) ? sums[t - 1] : 0;
    if (i0 < NB) g_bcur[i0] = base;
    if (i1 < NB) g_bcur[i1] = base + a0;
}

// ---------------- scatter edges into column buckets ----------------
// 2 edges/thread; per-bucket atomic cursors (1172 spread addresses).
__global__ __launch_bounds__(256) void k_bscatter(const int* __restrict__ erow,
                                                  const int* __restrict__ ecol,
                                                  const float* __restrict__ eval) {
    int t = blockIdx.x * blockDim.x + threadIdx.x;
    int e = t * 2;
    if (e >= NNZ) return;
    int2   cc = __ldcs(reinterpret_cast<const int2*>(ecol + e));
    int2   rr = __ldcs(reinterpret_cast<const int2*>(erow + e));
    float2 vv = __ldcs(reinterpret_cast<const float2*>(eval + e));
    int p0 = atomicAdd(&g_bcur[cc.x >> BSHIFT], 1);
    int p1 = atomicAdd(&g_bcur[cc.y >> BSHIFT], 1);
    g_scol[p0] = cc.x;
    g_srv [p0] = make_int2(rr.x, __float_as_int(vv.x));
    g_scol[p1] = cc.y;
    g_srv [p1] = make_int2(rr.y, __float_as_int(vv.y));
}

// ---------------- compact layer-3 edges from SORTED arrays ----------------
// 2 edges/thread, warp scan + one atomicAdd per block. Output stays col-ordered
// per-block (approximately), preserving gather locality for spmm3c.
__global__ __launch_bounds__(256) void k_compact() {
    __shared__ int wtot[8];
    __shared__ int bbase;

    int t = blockIdx.x * blockDim.x + threadIdx.x;
    int lane = threadIdx.x & 31;
    int wid  = threadIdx.x >> 5;

    int4 rv = make_int4(0, 0, 0, 0);
    int2 c2 = make_int2(0, 0);
    bool a0 = false, a1 = false;
    if (t * 2 < NNZ) {
        rv = __ldg(reinterpret_cast<const int4*>(g_srv) + t);
        c2 = __ldg(reinterpret_cast<const int2*>(g_scol) + t);
        a0 = g_needed[rv.x];
        a1 = g_needed[rv.z];
    }
    int cnt = (int)a0 + (int)a1;

    int inc = cnt;
#pragma unroll
    for (int o = 1; o < 32; o <<= 1) {
        int n = __shfl_up_sync(0xffffffffu, inc, o);
        if (lane >= o) inc += n;
    }
    if (lane == 31) wtot[wid] = inc;
    __syncthreads();
    if (threadIdx.x == 0) {
        int tot = 0;
#pragma unroll
        for (int w = 0; w < 8; ++w) { int x = wtot[w]; wtot[w] = tot; tot += x; }
        bbase = tot ? atomicAdd(&g_count, tot) : 0;
    }
    __syncthreads();

    if (cnt) {
        int pos = bbase + wtot[wid] + (inc - cnt);
        if (a0) { g_cc[pos] = c2.x; g_crv[pos] = make_int2(rv.x, rv.y); ++pos; }
        if (a1) { g_cc[pos] = c2.y; g_crv[pos] = make_int2(rv.z, rv.w); }
    }
}

// ---------------- init: normalize prefs -> h0 (fp16), zero rawA ----------------
__global__ __launch_bounds__(256) void k_init(const float* __restrict__ up,
                                              const float* __restrict__ ip) {
    int warp = blockIdx.x * (blockDim.x >> 5) + (threadIdx.x >> 5);
    int rbase = warp * 4;
    if (rbase >= N_NODES) return;
    int lane = threadIdx.x & 31;
    int sub  = lane >> 4;
    int j    = lane & 15;

    int r0 = rbase + sub;
    int r1 = r0 + 2;

    const float* s0 = (r0 < NUM_USERS) ? up + (size_t)r0 * C
                                       : ip + (size_t)(r0 - NUM_USERS) * C;
    const float* s1 = (r1 < NUM_USERS) ? up + (size_t)r1 * C
                                       : ip + (size_t)(r1 - NUM_USERS) * C;

    float4 v0 = __ldg(reinterpret_cast<const float4*>(s0) + j);
    float4 v1 = __ldg(reinterpret_cast<const float4*>(s1) + j);

    v0.x = lrelu(v0.x); v0.y = lrelu(v0.y); v0.z = lrelu(v0.z); v0.w = lrelu(v0.w);
    v1.x = lrelu(v1.x); v1.y = lrelu(v1.y); v1.z = lrelu(v1.z); v1.w = lrelu(v1.w);

    float i0 = 1.0f / fmaxf(sqrtf(seg16_sum(v0.x*v0.x + v0.y*v0.y + v0.z*v0.z + v0.w*v0.w)), EPS);
    float i1 = 1.0f / fmaxf(sqrtf(seg16_sum(v1.x*v1.x + v1.y*v1.y + v1.z*v1.z + v1.w*v1.w)), EPS);

    __half2 a0 = __floats2half2_rn(v0.x * i0, v0.y * i0);
    __half2 b0 = __floats2half2_rn(v0.z * i0, v0.w * i0);
    __half2 a1 = __floats2half2_rn(v1.x * i1, v1.y * i1);
    __half2 b1 = __floats2half2_rn(v1.z * i1, v1.w * i1);

    uint2* h0 = reinterpret_cast<uint2*>(g_h[0]);
    uint2* za = reinterpret_cast<uint2*>(g_rawA);
    h0[(size_t)r0 * 16 + j] =
        make_uint2(*reinterpret_cast<unsigned int*>(&a0), *reinterpret_cast<unsigned int*>(&b0));
    h0[(size_t)r1 * 16 + j] =
        make_uint2(*reinterpret_cast<unsigned int*>(&a1), *reinterpret_cast<unsigned int*>(&b1));
    za[(size_t)r0 * 16 + j] = make_uint2(0u, 0u);
    za[(size_t)r1 * 16 + j] = make_uint2(0u, 0u);
}

// ---------------- dense SpMM scatter (layers 1,2) over SORTED edges ----------------
// 8 threads/edge, adjacent sorted-edge pair per thread; col-bucketed order makes
// gathers L1-resident.
__global__ __launch_bounds__(256) void k_spmm(int layer) {
    const __half* __restrict__ p = (layer == 1) ? g_h[0] : g_h[1];
    __half* __restrict__ pn      = (layer == 1) ? g_rawA : g_rawB;

    int tid = blockIdx.x * blockDim.x + threadIdx.x;
    int g = tid >> 3;
    int q = tid & 7;
    if (g >= NNZ / 2) return;

    int2 cc = __ldg(reinterpret_cast<const int2*>(g_scol) + g);
    int4 rv = __ldg(reinterpret_cast<const int4*>(g_srv) + g);

    uint4 ha = __ldg(reinterpret_cast<const uint4*>(p + (size_t)cc.x * C + q * 8));
    uint4 hb = __ldg(reinterpret_cast<const uint4*>(p + (size_t)cc.y * C + q * 8));

    __half2 va = __float2half2_rn(__int_as_float(rv.y));
    __half2 vb = __float2half2_rn(__int_as_float(rv.w));

    unsigned int o0[4], o1[4];
    unsigned int* pa32 = reinterpret_cast<unsigned int*>(&ha);
    unsigned int* pb32 = reinterpret_cast<unsigned int*>(&hb);
#pragma unroll
    for (int k = 0; k < 4; ++k) {
        __half2 qa = __hmul2(*reinterpret_cast<__half2*>(&pa32[k]), va);
        __half2 qb = __hmul2(*reinterpret_cast<__half2*>(&pb32[k]), vb);
        o0[k] = *reinterpret_cast<unsigned int*>(&qa);
        o1[k] = *reinterpret_cast<unsigned int*>(&qb);
    }

    __half* d0 = pn + (size_t)rv.x * C + q * 8;
    __half* d1 = pn + (size_t)rv.z * C + q * 8;
    asm volatile("red.global.add.noftz.v4.f16x2 [%0], {%1,%2,%3,%4};"
                 :: "l"(d0), "r"(o0[0]), "r"(o0[1]), "r"(o0[2]), "r"(o0[3]) : "memory");
    asm volatile("red.global.add.noftz.v4.f16x2 [%0], {%1,%2,%3,%4};"
                 :: "l"(d1), "r"(o1[0]), "r"(o1[1]), "r"(o1[2]), "r"(o1[3]) : "memory");
}

// ---------------- compacted layer-3 SpMM: grid-stride over g_count edges ----------------
__global__ __launch_bounds__(256) void k_spmm3c() {
    const __half* __restrict__ p = g_h[2];
    __half* __restrict__ pn      = g_rawA;

    int cnt = g_count;
    int tid = blockIdx.x * blockDim.x + threadIdx.x;
    int G   = (gridDim.x * blockDim.x) >> 3;
    int q   = tid & 7;

    for (int e = tid >> 3; e < cnt; e += G) {
        int  c  = __ldg(g_cc + e);
        int2 rv = __ldg(g_crv + e);

        uint4 h = __ldg(reinterpret_cast<const uint4*>(p + (size_t)c * C + q * 8));
        __half2 vh = __float2half2_rn(__int_as_float(rv.y));
        unsigned int o[4];
        unsigned int* hh = reinterpret_cast<unsigned int*>(&h);
#pragma unroll
        for (int k = 0; k < 4; ++k) {
            __half2 qv = __hmul2(*reinterpret_cast<__half2*>(&hh[k]), vh);
            o[k] = *reinterpret_cast<unsigned int*>(&qv);
        }
        __half* d = pn + (size_t)rv.x * C + q * 8;
        asm volatile("red.global.add.noftz.v4.f16x2 [%0], {%1,%2,%3,%4};"
                     :: "l"(d), "r"(o[0]), "r"(o[1]), "r"(o[2]), "r"(o[3]) : "memory");
    }
}

// ---------------- norm: raw fp16 -> lrelu+l2norm -> fp16, zero next raw ----------------
__global__ __launch_bounds__(256) void k_norm(int layer) {
    const uint2* __restrict__ raw = reinterpret_cast<const uint2*>((layer == 1) ? g_rawA : g_rawB);
    uint2* __restrict__ hdst      = reinterpret_cast<uint2*>(g_h[layer]);
    uint2* __restrict__ rawz      = reinterpret_cast<uint2*>((layer == 1) ? g_rawB : g_rawA);

    int warp = blockIdx.x * (blockDim.x >> 5) + (threadIdx.x >> 5);
    int rbase = warp * 4;
    if (rbase >= N_NODES) return;
    int lane = threadIdx.x & 31;
    int sub  = lane >> 4;
    int j    = lane & 15;

    int r0 = rbase + sub;
    int r1 = r0 + 2;

    uint2 u0 = raw[(size_t)r0 * 16 + j];
    uint2 u1 = raw[(size_t)r1 * 16 + j];

    float2 x0 = __half22float2(*reinterpret_cast<__half2*>(&u0.x));
    float2 y0 = __half22float2(*reinterpret_cast<__half2*>(&u0.y));
    float2 x1 = __half22float2(*reinterpret_cast<__half2*>(&u1.x));
    float2 y1 = __half22float2(*reinterpret_cast<__half2*>(&u1.y));

    x0.x = lrelu(x0.x); x0.y = lrelu(x0.y); y0.x = lrelu(y0.x); y0.y = lrelu(y0.y);
    x1.x = lrelu(x1.x); x1.y = lrelu(x1.y); y1.x = lrelu(y1.x); y1.y = lrelu(y1.y);

    float i0 = 1.0f / fmaxf(sqrtf(seg16_sum(x0.x*x0.x + x0.y*x0.y + y0.x*y0.x + y0.y*y0.y)), EPS);
    float i1 = 1.0f / fmaxf(sqrtf(seg16_sum(x1.x*x1.x + x1.y*x1.y + y1.x*y1.x + y1.y*y1.y)), EPS);

    __half2 a0 = __floats2half2_rn(x0.x * i0, x0.y * i0);
    __half2 b0 = __floats2half2_rn(y0.x * i0, y0.y * i0);
    __half2 a1 = __floats2half2_rn(x1.x * i1, x1.y * i1);
    __half2 b1 = __floats2half2_rn(y1.x * i1, y1.y * i1);

    hdst[(size_t)r0 * 16 + j] =
        make_uint2(*reinterpret_cast<unsigned int*>(&a0), *reinterpret_cast<unsigned int*>(&b0));
    hdst[(size_t)r1 * 16 + j] =
        make_uint2(*reinterpret_cast<unsigned int*>(&a1), *reinterpret_cast<unsigned int*>(&b1));

    if (layer == 1 || g_needed[r0]) rawz[(size_t)r0 * 16 + j] = make_uint2(0u, 0u);
    if (layer == 1 || g_needed[r1]) rawz[(size_t)r1 * 16 + j] = make_uint2(0u, 0u);
}

// ---------------- scoring ----------------
__device__ __forceinline__ float2 merged_row(int row, int lane) {
    size_t idx = (size_t)row * 32 + lane;

    __half2 h0 = __ldg(&reinterpret_cast<const __half2*>(g_h[0])[idx]);
    __half2 h1 = __ldg(&reinterpret_cast<const __half2*>(g_h[1])[idx]);
    __half2 h2 = __ldg(&reinterpret_cast<const __half2*>(g_h[2])[idx]);
    float2 a3  = __half22float2(__ldg(&reinterpret_cast<const __half2*>(g_rawA)[idx]));

    a3.x = lrelu(a3.x);
    a3.y = lrelu(a3.y);
    float s = warp_sum(a3.x * a3.x + a3.y * a3.y);
    float inv = 1.0f / fmaxf(sqrtf(s), EPS);

    float2 f0 = __half22float2(h0);
    float2 f1 = __half22float2(h1);
    float2 f2 = __half22float2(h2);

    float2 m;
    m.x = f0.x + f1.x + f2.x + a3.x * inv;
    m.y = f0.y + f1.y + f2.y + a3.y * inv;
    return m;
}

__global__ __launch_bounds__(256) void k_score(const int* __restrict__ users,
                                               const int* __restrict__ adj,
                                               const int* __restrict__ weak,
                                               const int* __restrict__ strong,
                                               float* __restrict__ out) {
    int b = blockIdx.x * (blockDim.x >> 5) + (threadIdx.x >> 5);
    if (b >= BATCH) return;
    int lane = threadIdx.x & 31;

    float2 uv = merged_row(users[b], lane);
    float2 m0 = merged_row(NUM_USERS + adj[b], lane);
    float2 m1 = merged_row(NUM_USERS + weak[b], lane);
    float2 m2 = merged_row(NUM_USERS + strong[b], lane);

    float d0 = warp_sum(uv.x * m0.x + uv.y * m0.y);
    float d1 = warp_sum(uv.x * m1.x + uv.y * m1.y);
    float d2 = warp_sum(uv.x * m2.x + uv.y * m2.y);

    if (lane == 0) {
        out[0 * BATCH + b] = 1.0f / (1.0f + expf(-d0 * (1.0f / 16.0f)));
        out[1 * BATCH + b] = 1.0f / (1.0f + expf(-d1 * (1.0f / 16.0f)));
        out[2 * BATCH + b] = 1.0f / (1.0f + expf(-d2 * (1.0f / 16.0f)));
    }
}

extern "C" void kernel_launch(void* const* d_in, const int* in_sizes, int n_in,
                              void* d_out, int out_size) {
    const int*   users  = (const int*)d_in[0];
    const int*   adj    = (const int*)d_in[1];
    const int*   weak   = (const int*)d_in[2];
    const int*   strong = (const int*)d_in[3];
    const int*   erow   = (const int*)d_in[4];
    const int*   ecol   = (const int*)d_in[5];
    const float* eval   = (const float*)d_in[6];
    const float* up     = (const float*)d_in[7];
    const float* ip     = (const float*)d_in[8];
    float* out = (float*)d_out;

    const int ROW4_BLOCKS = (N_NODES + 31) / 32;
    const int SPMM_BLOCKS = ((NNZ / 2) * 8 + 255) / 256;

    // prologue: bitmap + column-bucket sort of the edge list (reused 3x)
    k_zero_pro<<<(N_NODES / 4 + 255) / 256, 256>>>();
    k_mark<<<(BATCH + 255) / 256, 256>>>(users, adj, weak, strong);
    k_bhist<<<256, 256>>>(ecol);
    k_bscan<<<1, 1024>>>();
    k_bscatter<<<(NNZ / 2 + 255) / 256, 256>>>(erow, ecol, eval);
    k_compact<<<(NNZ / 2 + 255) / 256, 256>>>();

    k_init<<<ROW4_BLOCKS, 256>>>(up, ip);

    k_spmm<<<SPMM_BLOCKS, 256>>>(1);     // h0 -> rawA (sorted edges)
    k_norm<<<ROW4_BLOCKS, 256>>>(1);     // rawA -> h1, zero rawB
    k_spmm<<<SPMM_BLOCKS, 256>>>(2);     // h1 -> rawB (sorted edges)
    k_norm<<<ROW4_BLOCKS, 256>>>(2);     // rawB -> h2, zero rawA@needed
    k_spmm3c<<<2048, 256>>>();           // compacted sorted -> rawA

    k_score<<<(BATCH + 7) / 8, 256>>>(users, adj, weak, strong, out);
}

// round 15
// speedup vs baseline: 1.8422x; 1.8422x over previous
#include <cuda_runtime.h>
#include <cuda_fp16.h>
#include <cstdint>

#define NUM_USERS 100000
#define NUM_ITEMS 50000
#define N_NODES   150000
#define C         64
#define NNZ       2400000
#define BATCH     8192
#define NEG_SLOPE 0.1f
#define EPS       1e-12f

// Normalized layer outputs p0,p1,p2 in fp16 (gather/score sources).
__device__ __half g_h[3][(size_t)N_NODES * C];
// fp16 RED accumulation targets. Layer1->rawA, 2->rawB, 3->rawA.
__device__ __half g_rawA[(size_t)N_NODES * C];
__device__ __half g_rawB[(size_t)N_NODES * C];
// Rows where layer-3 output is actually consumed (batch rows).
__device__ unsigned char g_needed[N_NODES];
// Compacted layer-3 edge list (destinations in needed set).
__device__ int   g_cr[NNZ];
__device__ int   g_cc[NNZ];
__device__ float g_cv[NNZ];
__device__ int   g_count;

__device__ __forceinline__ float lrelu(float x) {
    return x >= 0.0f ? x : NEG_SLOPE * x;
}

__device__ __forceinline__ float warp_sum(float s) {
#pragma unroll
    for (int o = 16; o; o >>= 1) s += __shfl_xor_sync(0xffffffffu, s, o);
    return s;
}

__device__ __forceinline__ float seg16_sum(float s) {
#pragma unroll
    for (int o = 8; o; o >>= 1) s += __shfl_xor_sync(0xffffffffu, s, o);
    return s;
}

// ---------------- needed-row bitmap ----------------
__global__ __launch_bounds__(256) void k_zero_needed() {
    int i = blockIdx.x * blockDim.x + threadIdx.x;
    if (i == 0) g_count = 0;
    if (i * 4 < N_NODES)
        reinterpret_cast<unsigned int*>(g_needed)[i] = 0u;
}

__global__ __launch_bounds__(256) void k_mark(const int* __restrict__ users,
                                              const int* __restrict__ adj,
                                              const int* __restrict__ weak,
                                              const int* __restrict__ strong) {
    int i = blockIdx.x * blockDim.x + threadIdx.x;
    if (i >= BATCH) return;
    g_needed[users[i]] = 1;
    g_needed[NUM_USERS + adj[i]] = 1;
    g_needed[NUM_USERS + weak[i]] = 1;
    g_needed[NUM_USERS + strong[i]] = 1;
}

// ---------------- compact layer-3 edges ----------------
// 4 edges/thread (int4 streaming loads), warp scan + one atomicAdd per block.
__global__ __launch_bounds__(256) void k_compact(const int* __restrict__ erow,
                                                 const int* __restrict__ ecol,
                                                 const float* __restrict__ eval) {
    __shared__ int wtot[8];
    __shared__ int bbase;

    int t = blockIdx.x * blockDim.x + threadIdx.x;
    int e = t * 4;
    int lane = threadIdx.x & 31;
    int wid  = threadIdx.x >> 5;

    int4 r = make_int4(0, 0, 0, 0);
    bool a0 = false, a1 = false, a2 = false, a3 = false;
    if (e < NNZ) {
        r = __ldcs(reinterpret_cast<const int4*>(erow + e));
        a0 = g_needed[r.x]; a1 = g_needed[r.y];
        a2 = g_needed[r.z]; a3 = g_needed[r.w];
    }
    int cnt = (int)a0 + (int)a1 + (int)a2 + (int)a3;

    int inc = cnt;
#pragma unroll
    for (int o = 1; o < 32; o <<= 1) {
        int n = __shfl_up_sync(0xffffffffu, inc, o);
        if (lane >= o) inc += n;
    }
    if (lane == 31) wtot[wid] = inc;
    __syncthreads();
    if (threadIdx.x == 0) {
        int tot = 0;
#pragma unroll
        for (int w = 0; w < 8; ++w) { int x = wtot[w]; wtot[w] = tot; tot += x; }
        bbase = tot ? atomicAdd(&g_count, tot) : 0;
    }
    __syncthreads();

    if (cnt) {
        int pos = bbase + wtot[wid] + (inc - cnt);
        int4   c = __ldcs(reinterpret_cast<const int4*>(ecol + e));
        float4 v = __ldcs(reinterpret_cast<const float4*>(eval + e));
        if (a0) { g_cr[pos] = r.x; g_cc[pos] = c.x; g_cv[pos] = v.x; ++pos; }
        if (a1) { g_cr[pos] = r.y; g_cc[pos] = c.y; g_cv[pos] = v.y; ++pos; }
        if (a2) { g_cr[pos] = r.z; g_cc[pos] = c.z; g_cv[pos] = v.z; ++pos; }
        if (a3) { g_cr[pos] = r.w; g_cc[pos] = c.w; g_cv[pos] = v.w; }
    }
}

// ---------------- init: normalize prefs -> h0 (fp16), zero rawA ----------------
// 16 lanes/row, 4 rows/warp.
__global__ __launch_bounds__(256) void k_init(const float* __restrict__ up,
                                              const float* __restrict__ ip) {
    int warp = blockIdx.x * (blockDim.x >> 5) + (threadIdx.x >> 5);
    int rbase = warp * 4;
    if (rbase >= N_NODES) return;
    int lane = threadIdx.x & 31;
    int sub  = lane >> 4;
    int j    = lane & 15;

    int r0 = rbase + sub;
    int r1 = r0 + 2;

    const float* s0 = (r0 < NUM_USERS) ? up + (size_t)r0 * C
                                       : ip + (size_t)(r0 - NUM_USERS) * C;
    const float* s1 = (r1 < NUM_USERS) ? up + (size_t)r1 * C
                                       : ip + (size_t)(r1 - NUM_USERS) * C;

    float4 v0 = __ldg(reinterpret_cast<const float4*>(s0) + j);
    float4 v1 = __ldg(reinterpret_cast<const float4*>(s1) + j);

    v0.x = lrelu(v0.x); v0.y = lrelu(v0.y); v0.z = lrelu(v0.z); v0.w = lrelu(v0.w);
    v1.x = lrelu(v1.x); v1.y = lrelu(v1.y); v1.z = lrelu(v1.z); v1.w = lrelu(v1.w);

    float i0 = 1.0f / fmaxf(sqrtf(seg16_sum(v0.x*v0.x + v0.y*v0.y + v0.z*v0.z + v0.w*v0.w)), EPS);
    float i1 = 1.0f / fmaxf(sqrtf(seg16_sum(v1.x*v1.x + v1.y*v1.y + v1.z*v1.z + v1.w*v1.w)), EPS);

    __half2 a0 = __floats2half2_rn(v0.x * i0, v0.y * i0);
    __half2 b0 = __floats2half2_rn(v0.z * i0, v0.w * i0);
    __half2 a1 = __floats2half2_rn(v1.x * i1, v1.y * i1);
    __half2 b1 = __floats2half2_rn(v1.z * i1, v1.w * i1);

    uint2* h0 = reinterpret_cast<uint2*>(g_h[0]);
    uint2* za = reinterpret_cast<uint2*>(g_rawA);
    h0[(size_t)r0 * 16 + j] =
        make_uint2(*reinterpret_cast<unsigned int*>(&a0), *reinterpret_cast<unsigned int*>(&b0));
    h0[(size_t)r1 * 16 + j] =
        make_uint2(*reinterpret_cast<unsigned int*>(&a1), *reinterpret_cast<unsigned int*>(&b1));
    za[(size_t)r0 * 16 + j] = make_uint2(0u, 0u);
    za[(size_t)r1 * 16 + j] = make_uint2(0u, 0u);
}

// ---------------- dense SpMM scatter (layers 1,2) ----------------
// 8 threads/edge, adjacent-edge pair per thread; vectorized edge metadata
// (__ldcs, evict-first) and fp16 HMUL2 inner math.
__global__ __launch_bounds__(256) void k_spmm(const int* __restrict__ erow,
                                              const int* __restrict__ ecol,
                                              const float* __restrict__ eval,
                                              int layer) {
    const __half* __restrict__ p = (layer == 1) ? g_h[0] : g_h[1];
    __half* __restrict__ pn      = (layer == 1) ? g_rawA : g_rawB;

    int tid = blockIdx.x * blockDim.x + threadIdx.x;
    int g = tid >> 3;
    int q = tid & 7;
    if (g >= NNZ / 2) return;
    int e = g * 2;

    int2   rr = __ldcs(reinterpret_cast<const int2*>(erow + e));
    int2   cc = __ldcs(reinterpret_cast<const int2*>(ecol + e));
    float2 vv = __ldcs(reinterpret_cast<const float2*>(eval + e));

    uint4 ha = __ldg(reinterpret_cast<const uint4*>(p + (size_t)cc.x * C + q * 8));
    uint4 hb = __ldg(reinterpret_cast<const uint4*>(p + (size_t)cc.y * C + q * 8));

    __half2 va = __float2half2_rn(vv.x);
    __half2 vb = __float2half2_rn(vv.y);

    unsigned int o0[4], o1[4];
    unsigned int* pa32 = reinterpret_cast<unsigned int*>(&ha);
    unsigned int* pb32 = reinterpret_cast<unsigned int*>(&hb);
#pragma unroll
    for (int k = 0; k < 4; ++k) {
        __half2 qa = __hmul2(*reinterpret_cast<__half2*>(&pa32[k]), va);
        __half2 qb = __hmul2(*reinterpret_cast<__half2*>(&pb32[k]), vb);
        o0[k] = *reinterpret_cast<unsigned int*>(&qa);
        o1[k] = *reinterpret_cast<unsigned int*>(&qb);
    }

    __half* d0 = pn + (size_t)rr.x * C + q * 8;
    __half* d1 = pn + (size_t)rr.y * C + q * 8;
    asm volatile("red.global.add.noftz.v4.f16x2 [%0], {%1,%2,%3,%4};"
                 :: "l"(d0), "r"(o0[0]), "r"(o0[1]), "r"(o0[2]), "r"(o0[3]) : "memory");
    asm volatile("red.global.add.noftz.v4.f16x2 [%0], {%1,%2,%3,%4};"
                 :: "l"(d1), "r"(o1[0]), "r"(o1[1]), "r"(o1[2]), "r"(o1[3]) : "memory");
}

// ---------------- compacted layer-3 SpMM: grid-stride over g_count edges ----------------
__global__ __launch_bounds__(256) void k_spmm3c() {
    const __half* __restrict__ p = g_h[2];
    __half* __restrict__ pn      = g_rawA;

    int cnt = g_count;
    int tid = blockIdx.x * blockDim.x + threadIdx.x;
    int G   = (gridDim.x * blockDim.x) >> 3;
    int q   = tid & 7;

    for (int e = tid >> 3; e < cnt; e += G) {
        int   r = __ldcs(g_cr + e);
        int   c = __ldcs(g_cc + e);
        float v = __ldcs(g_cv + e);

        uint4 h = __ldg(reinterpret_cast<const uint4*>(p + (size_t)c * C + q * 8));
        __half2 vh = __float2half2_rn(v);
        unsigned int o[4];
        unsigned int* hh = reinterpret_cast<unsigned int*>(&h);
#pragma unroll
        for (int k = 0; k < 4; ++k) {
            __half2 qv = __hmul2(*reinterpret_cast<__half2*>(&hh[k]), vh);
            o[k] = *reinterpret_cast<unsigned int*>(&qv);
        }
        __half* d = pn + (size_t)r * C + q * 8;
        asm volatile("red.global.add.noftz.v4.f16x2 [%0], {%1,%2,%3,%4};"
                     :: "l"(d), "r"(o[0]), "r"(o[1]), "r"(o[2]), "r"(o[3]) : "memory");
    }
}

// ---------------- norm: raw fp16 -> lrelu+l2norm -> fp16, zero next raw ----------------
// 16 lanes/row, 4 rows/warp.
__global__ __launch_bounds__(256) void k_norm(int layer) {
    const uint2* __restrict__ raw = reinterpret_cast<const uint2*>((layer == 1) ? g_rawA : g_rawB);
    uint2* __restrict__ hdst      = reinterpret_cast<uint2*>(g_h[layer]);
    uint2* __restrict__ rawz      = reinterpret_cast<uint2*>((layer == 1) ? g_rawB : g_rawA);

    int warp = blockIdx.x * (blockDim.x >> 5) + (threadIdx.x >> 5);
    int rbase = warp * 4;
    if (rbase >= N_NODES) return;
    int lane = threadIdx.x & 31;
    int sub  = lane >> 4;
    int j    = lane & 15;

    int r0 = rbase + sub;
    int r1 = r0 + 2;

    uint2 u0 = raw[(size_t)r0 * 16 + j];
    uint2 u1 = raw[(size_t)r1 * 16 + j];

    float2 x0 = __half22float2(*reinterpret_cast<__half2*>(&u0.x));
    float2 y0 = __half22float2(*reinterpret_cast<__half2*>(&u0.y));
    float2 x1 = __half22float2(*reinterpret_cast<__half2*>(&u1.x));
    float2 y1 = __half22float2(*reinterpret_cast<__half2*>(&u1.y));

    x0.x = lrelu(x0.x); x0.y = lrelu(x0.y); y0.x = lrelu(y0.x); y0.y = lrelu(y0.y);
    x1.x = lrelu(x1.x); x1.y = lrelu(x1.y); y1.x = lrelu(y1.x); y1.y = lrelu(y1.y);

    float i0 = 1.0f / fmaxf(sqrtf(seg16_sum(x0.x*x0.x + x0.y*x0.y + y0.x*y0.x + y0.y*y0.y)), EPS);
    float i1 = 1.0f / fmaxf(sqrtf(seg16_sum(x1.x*x1.x + x1.y*x1.y + y1.x*y1.x + y1.y*y1.y)), EPS);

    __half2 a0 = __floats2half2_rn(x0.x * i0, x0.y * i0);
    __half2 b0 = __floats2half2_rn(y0.x * i0, y0.y * i0);
    __half2 a1 = __floats2half2_rn(x1.x * i1, x1.y * i1);
    __half2 b1 = __floats2half2_rn(y1.x * i1, y1.y * i1);

    hdst[(size_t)r0 * 16 + j] =
        make_uint2(*reinterpret_cast<unsigned int*>(&a0), *reinterpret_cast<unsigned int*>(&b0));
    hdst[(size_t)r1 * 16 + j] =
        make_uint2(*reinterpret_cast<unsigned int*>(&a1), *reinterpret_cast<unsigned int*>(&b1));

    if (layer == 1 || g_needed[r0]) rawz[(size_t)r0 * 16 + j] = make_uint2(0u, 0u);
    if (layer == 1 || g_needed[r1]) rawz[(size_t)r1 * 16 + j] = make_uint2(0u, 0u);
}

// ---------------- scoring ----------------
__device__ __forceinline__ float2 merged_row(int row, int lane) {
    size_t idx = (size_t)row * 32 + lane;

    __half2 h0 = __ldg(&reinterpret_cast<const __half2*>(g_h[0])[idx]);
    __half2 h1 = __ldg(&reinterpret_cast<const __half2*>(g_h[1])[idx]);
    __half2 h2 = __ldg(&reinterpret_cast<const __half2*>(g_h[2])[idx]);
    float2 a3  = __half22float2(__ldg(&reinterpret_cast<const __half2*>(g_rawA)[idx]));

    a3.x = lrelu(a3.x);
    a3.y = lrelu(a3.y);
    float s = warp_sum(a3.x * a3.x + a3.y * a3.y);
    float inv = 1.0f / fmaxf(sqrtf(s), EPS);

    float2 f0 = __half22float2(h0);
    float2 f1 = __half22float2(h1);
    float2 f2 = __half22float2(h2);

    float2 m;
    m.x = f0.x + f1.x + f2.x + a3.x * inv;
    m.y = f0.y + f1.y + f2.y + a3.y * inv;
    return m;
}

__global__ __launch_bounds__(256) void k_score(const int* __restrict__ users,
                                               const int* __restrict__ adj,
                                               const int* __restrict__ weak,
                                               const int* __restrict__ strong,
                                               float* __restrict__ out) {
    int b = blockIdx.x * (blockDim.x >> 5) + (threadIdx.x >> 5);
    if (b >= BATCH) return;
    int lane = threadIdx.x & 31;

    float2 uv = merged_row(users[b], lane);
    float2 m0 = merged_row(NUM_USERS + adj[b], lane);
    float2 m1 = merged_row(NUM_USERS + weak[b], lane);
    float2 m2 = merged_row(NUM_USERS + strong[b], lane);

    float d0 = warp_sum(uv.x * m0.x + uv.y * m0.y);
    float d1 = warp_sum(uv.x * m1.x + uv.y * m1.y);
    float d2 = warp_sum(uv.x * m2.x + uv.y * m2.y);

    if (lane == 0) {
        out[0 * BATCH + b] = 1.0f / (1.0f + expf(-d0 * (1.0f / 16.0f)));
        out[1 * BATCH + b] = 1.0f / (1.0f + expf(-d1 * (1.0f / 16.0f)));
        out[2 * BATCH + b] = 1.0f / (1.0f + expf(-d2 * (1.0f / 16.0f)));
    }
}

extern "C" void kernel_launch(void* const* d_in, const int* in_sizes, int n_in,
                              void* d_out, int out_size) {
    const int*   users  = (const int*)d_in[0];
    const int*   adj    = (const int*)d_in[1];
    const int*   weak   = (const int*)d_in[2];
    const int*   strong = (const int*)d_in[3];
    const int*   erow   = (const int*)d_in[4];
    const int*   ecol   = (const int*)d_in[5];
    const float* eval   = (const float*)d_in[6];
    const float* up     = (const float*)d_in[7];
    const float* ip     = (const float*)d_in[8];
    float* out = (float*)d_out;

    const int ROW4_BLOCKS = (N_NODES + 31) / 32;
    const int SPMM_BLOCKS = ((NNZ / 2) * 8 + 255) / 256;

    k_zero_needed<<<(N_NODES / 4 + 255) / 256, 256>>>();
    k_mark<<<(BATCH + 255) / 256, 256>>>(users, adj, weak, strong);
    k_compact<<<(NNZ / 4 + 255) / 256, 256>>>(erow, ecol, eval);

    k_init<<<ROW4_BLOCKS, 256>>>(up, ip);

    k_spmm<<<SPMM_BLOCKS, 256>>>(erow, ecol, eval, 1);   // h0 -> rawA
    k_norm<<<ROW4_BLOCKS, 256>>>(1);                     // rawA -> h1, zero rawB
    k_spmm<<<SPMM_BLOCKS, 256>>>(erow, ecol, eval, 2);   // h1 -> rawB
    k_norm<<<ROW4_BLOCKS, 256>>>(2);                     // rawB -> h2, zero rawA@needed
    k_spmm3c<<<2048, 256>>>();                           // compacted -> rawA

    k_score<<<(BATCH + 7) / 8, 256>>>(users, adj, weak, strong, out);
}

// round 16
// speedup vs baseline: 1.9953x; 1.0831x over previous
#include <cuda_runtime.h>
#include <cuda_fp16.h>
#include <cstdint>

#define NUM_USERS 100000
#define NUM_ITEMS 50000
#define N_NODES   150000
#define C         64
#define NNZ       2400000
#define BATCH     8192
#define NEG_SLOPE 0.1f
#define EPS       1e-12f

// Normalized layer outputs p0,p1,p2 in fp16 (gather/score sources).
__device__ __half g_h[3][(size_t)N_NODES * C];
// fp16 RED accumulation targets. Layer1->rawA, 2->rawB, 3->rawA.
__device__ __half g_rawA[(size_t)N_NODES * C];
__device__ __half g_rawB[(size_t)N_NODES * C];
// Rows where layer-3 output is actually consumed (batch rows).
__device__ unsigned char g_needed[N_NODES];
// Compacted layer-3 edge list (destinations in needed set).
__device__ int   g_cr[NNZ];
__device__ int   g_cc[NNZ];
__device__ float g_cv[NNZ];
__device__ int   g_count;

__device__ __forceinline__ float lrelu(float x) {
    return x >= 0.0f ? x : NEG_SLOPE * x;
}

__device__ __forceinline__ float warp_sum(float s) {
#pragma unroll
    for (int o = 16; o; o >>= 1) s += __shfl_xor_sync(0xffffffffu, s, o);
    return s;
}

__device__ __forceinline__ float seg16_sum(float s) {
#pragma unroll
    for (int o = 8; o; o >>= 1) s += __shfl_xor_sync(0xffffffffu, s, o);
    return s;
}

// ---------------- needed-row bitmap ----------------
__global__ __launch_bounds__(256) void k_zero_needed() {
    int i = blockIdx.x * blockDim.x + threadIdx.x;
    if (i == 0) g_count = 0;
    if (i * 4 < N_NODES)
        reinterpret_cast<unsigned int*>(g_needed)[i] = 0u;
}

__global__ __launch_bounds__(256) void k_mark(const int* __restrict__ users,
                                              const int* __restrict__ adj,
                                              const int* __restrict__ weak,
                                              const int* __restrict__ strong) {
    int i = blockIdx.x * blockDim.x + threadIdx.x;
    if (i >= BATCH) return;
    g_needed[users[i]] = 1;
    g_needed[NUM_USERS + adj[i]] = 1;
    g_needed[NUM_USERS + weak[i]] = 1;
    g_needed[NUM_USERS + strong[i]] = 1;
}

// ---------------- compact layer-3 edges ----------------
// 4 edges/thread (int4 loads), warp scan + one atomicAdd per block.
__global__ __launch_bounds__(256) void k_compact(const int* __restrict__ erow,
                                                 const int* __restrict__ ecol,
                                                 const float* __restrict__ eval) {
    __shared__ int wtot[8];
    __shared__ int bbase;

    int t = blockIdx.x * blockDim.x + threadIdx.x;
    int e = t * 4;
    int lane = threadIdx.x & 31;
    int wid  = threadIdx.x >> 5;

    int4 r = make_int4(0, 0, 0, 0);
    bool a0 = false, a1 = false, a2 = false, a3 = false;
    if (e < NNZ) {
        r = __ldg(reinterpret_cast<const int4*>(erow + e));
        a0 = g_needed[r.x]; a1 = g_needed[r.y];
        a2 = g_needed[r.z]; a3 = g_needed[r.w];
    }
    int cnt = (int)a0 + (int)a1 + (int)a2 + (int)a3;

    int inc = cnt;
#pragma unroll
    for (int o = 1; o < 32; o <<= 1) {
        int n = __shfl_up_sync(0xffffffffu, inc, o);
        if (lane >= o) inc += n;
    }
    if (lane == 31) wtot[wid] = inc;
    __syncthreads();
    if (threadIdx.x == 0) {
        int tot = 0;
#pragma unroll
        for (int w = 0; w < 8; ++w) { int x = wtot[w]; wtot[w] = tot; tot += x; }
        bbase = tot ? atomicAdd(&g_count, tot) : 0;
    }
    __syncthreads();

    if (cnt) {
        int pos = bbase + wtot[wid] + (inc - cnt);
        int4   c = __ldg(reinterpret_cast<const int4*>(ecol + e));
        float4 v = __ldg(reinterpret_cast<const float4*>(eval + e));
        if (a0) { g_cr[pos] = r.x; g_cc[pos] = c.x; g_cv[pos] = v.x; ++pos; }
        if (a1) { g_cr[pos] = r.y; g_cc[pos] = c.y; g_cv[pos] = v.y; ++pos; }
        if (a2) { g_cr[pos] = r.z; g_cc[pos] = c.z; g_cv[pos] = v.z; ++pos; }
        if (a3) { g_cr[pos] = r.w; g_cc[pos] = c.w; g_cv[pos] = v.w; }
    }
}

// ---------------- init: normalize prefs -> h0 (fp16), zero rawA ----------------
// 16 lanes/row, 4 rows/warp.
__global__ __launch_bounds__(256) void k_init(const float* __restrict__ up,
                                              const float* __restrict__ ip) {
    int warp = blockIdx.x * (blockDim.x >> 5) + (threadIdx.x >> 5);
    int rbase = warp * 4;
    if (rbase >= N_NODES) return;
    int lane = threadIdx.x & 31;
    int sub  = lane >> 4;
    int j    = lane & 15;

    int r0 = rbase + sub;
    int r1 = r0 + 2;

    const float* s0 = (r0 < NUM_USERS) ? up + (size_t)r0 * C
                                       : ip + (size_t)(r0 - NUM_USERS) * C;
    const float* s1 = (r1 < NUM_USERS) ? up + (size_t)r1 * C
                                       : ip + (size_t)(r1 - NUM_USERS) * C;

    float4 v0 = __ldg(reinterpret_cast<const float4*>(s0) + j);
    float4 v1 = __ldg(reinterpret_cast<const float4*>(s1) + j);

    v0.x = lrelu(v0.x); v0.y = lrelu(v0.y); v0.z = lrelu(v0.z); v0.w = lrelu(v0.w);
    v1.x = lrelu(v1.x); v1.y = lrelu(v1.y); v1.z = lrelu(v1.z); v1.w = lrelu(v1.w);

    float i0 = 1.0f / fmaxf(sqrtf(seg16_sum(v0.x*v0.x + v0.y*v0.y + v0.z*v0.z + v0.w*v0.w)), EPS);
    float i1 = 1.0f / fmaxf(sqrtf(seg16_sum(v1.x*v1.x + v1.y*v1.y + v1.z*v1.z + v1.w*v1.w)), EPS);

    __half2 a0 = __floats2half2_rn(v0.x * i0, v0.y * i0);
    __half2 b0 = __floats2half2_rn(v0.z * i0, v0.w * i0);
    __half2 a1 = __floats2half2_rn(v1.x * i1, v1.y * i1);
    __half2 b1 = __floats2half2_rn(v1.z * i1, v1.w * i1);

    uint2* h0 = reinterpret_cast<uint2*>(g_h[0]);
    uint2* za = reinterpret_cast<uint2*>(g_rawA);
    h0[(size_t)r0 * 16 + j] =
        make_uint2(*reinterpret_cast<unsigned int*>(&a0), *reinterpret_cast<unsigned int*>(&b0));
    h0[(size_t)r1 * 16 + j] =
        make_uint2(*reinterpret_cast<unsigned int*>(&a1), *reinterpret_cast<unsigned int*>(&b1));
    za[(size_t)r0 * 16 + j] = make_uint2(0u, 0u);
    za[(size_t)r1 * 16 + j] = make_uint2(0u, 0u);
}

// ---------------- dense SpMM scatter (layers 1,2) ----------------
// 8 threads/edge, adjacent-edge pair per thread; vectorized edge metadata
// (__ldcs, evict-first) and fp16 HMUL2 inner math.
__global__ __launch_bounds__(256) void k_spmm(const int* __restrict__ erow,
                                              const int* __restrict__ ecol,
                                              const float* __restrict__ eval,
                                              int layer) {
    const __half* __restrict__ p = (layer == 1) ? g_h[0] : g_h[1];
    __half* __restrict__ pn      = (layer == 1) ? g_rawA : g_rawB;

    int tid = blockIdx.x * blockDim.x + threadIdx.x;
    int g = tid >> 3;
    int q = tid & 7;
    if (g >= NNZ / 2) return;
    int e = g * 2;

    int2   rr = __ldcs(reinterpret_cast<const int2*>(erow + e));
    int2   cc = __ldcs(reinterpret_cast<const int2*>(ecol + e));
    float2 vv = __ldcs(reinterpret_cast<const float2*>(eval + e));

    uint4 ha = __ldg(reinterpret_cast<const uint4*>(p + (size_t)cc.x * C + q * 8));
    uint4 hb = __ldg(reinterpret_cast<const uint4*>(p + (size_t)cc.y * C + q * 8));

    __half2 va = __float2half2_rn(vv.x);
    __half2 vb = __float2half2_rn(vv.y);

    unsigned int o0[4], o1[4];
    unsigned int* pa32 = reinterpret_cast<unsigned int*>(&ha);
    unsigned int* pb32 = reinterpret_cast<unsigned int*>(&hb);
#pragma unroll
    for (int k = 0; k < 4; ++k) {
        __half2 qa = __hmul2(*reinterpret_cast<__half2*>(&pa32[k]), va);
        __half2 qb = __hmul2(*reinterpret_cast<__half2*>(&pb32[k]), vb);
        o0[k] = *reinterpret_cast<unsigned int*>(&qa);
        o1[k] = *reinterpret_cast<unsigned int*>(&qb);
    }

    __half* d0 = pn + (size_t)rr.x * C + q * 8;
    __half* d1 = pn + (size_t)rr.y * C + q * 8;
    asm volatile("red.global.add.noftz.v4.f16x2 [%0], {%1,%2,%3,%4};"
                 :: "l"(d0), "r"(o0[0]), "r"(o0[1]), "r"(o0[2]), "r"(o0[3]) : "memory");
    asm volatile("red.global.add.noftz.v4.f16x2 [%0], {%1,%2,%3,%4};"
                 :: "l"(d1), "r"(o1[0]), "r"(o1[1]), "r"(o1[2]), "r"(o1[3]) : "memory");
}

// ---------------- compacted layer-3 SpMM: grid-stride over g_count edges ----------------
__global__ __launch_bounds__(256) void k_spmm3c() {
    const __half* __restrict__ p = g_h[2];
    __half* __restrict__ pn      = g_rawA;

    int cnt = g_count;
    int tid = blockIdx.x * blockDim.x + threadIdx.x;
    int G   = (gridDim.x * blockDim.x) >> 3;
    int q   = tid & 7;

    for (int e = tid >> 3; e < cnt; e += G) {
        int   r = g_cr[e];
        int   c = g_cc[e];
        float v = g_cv[e];

        uint4 h = __ldg(reinterpret_cast<const uint4*>(p + (size_t)c * C + q * 8));
        __half2 vh = __float2half2_rn(v);
        unsigned int o[4];
        unsigned int* hh = reinterpret_cast<unsigned int*>(&h);
#pragma unroll
        for (int k = 0; k < 4; ++k) {
            __half2 qv = __hmul2(*reinterpret_cast<__half2*>(&hh[k]), vh);
            o[k] = *reinterpret_cast<unsigned int*>(&qv);
        }
        __half* d = pn + (size_t)r * C + q * 8;
        asm volatile("red.global.add.noftz.v4.f16x2 [%0], {%1,%2,%3,%4};"
                     :: "l"(d), "r"(o[0]), "r"(o[1]), "r"(o[2]), "r"(o[3]) : "memory");
    }
}

// ---------------- norm: raw fp16 -> lrelu+l2norm -> fp16, zero next raw ----------------
// 16 lanes/row, 4 rows/warp.
__global__ __launch_bounds__(256) void k_norm(int layer) {
    const uint2* __restrict__ raw = reinterpret_cast<const uint2*>((layer == 1) ? g_rawA : g_rawB);
    uint2* __restrict__ hdst      = reinterpret_cast<uint2*>(g_h[layer]);
    uint2* __restrict__ rawz      = reinterpret_cast<uint2*>((layer == 1) ? g_rawB : g_rawA);

    int warp = blockIdx.x * (blockDim.x >> 5) + (threadIdx.x >> 5);
    int rbase = warp * 4;
    if (rbase >= N_NODES) return;
    int lane = threadIdx.x & 31;
    int sub  = lane >> 4;
    int j    = lane & 15;

    int r0 = rbase + sub;
    int r1 = r0 + 2;

    uint2 u0 = raw[(size_t)r0 * 16 + j];
    uint2 u1 = raw[(size_t)r1 * 16 + j];

    float2 x0 = __half22float2(*reinterpret_cast<__half2*>(&u0.x));
    float2 y0 = __half22float2(*reinterpret_cast<__half2*>(&u0.y));
    float2 x1 = __half22float2(*reinterpret_cast<__half2*>(&u1.x));
    float2 y1 = __half22float2(*reinterpret_cast<__half2*>(&u1.y));

    x0.x = lrelu(x0.x); x0.y = lrelu(x0.y); y0.x = lrelu(y0.x); y0.y = lrelu(y0.y);
    x1.x = lrelu(x1.x); x1.y = lrelu(x1.y); y1.x = lrelu(y1.x); y1.y = lrelu(y1.y);

    float i0 = 1.0f / fmaxf(sqrtf(seg16_sum(x0.x*x0.x + x0.y*x0.y + y0.x*y0.x + y0.y*y0.y)), EPS);
    float i1 = 1.0f / fmaxf(sqrtf(seg16_sum(x1.x*x1.x + x1.y*x1.y + y1.x*y1.x + y1.y*y1.y)), EPS);

    __half2 a0 = __floats2half2_rn(x0.x * i0, x0.y * i0);
    __half2 b0 = __floats2half2_rn(y0.x * i0, y0.y * i0);
    __half2 a1 = __floats2half2_rn(x1.x * i1, x1.y * i1);
    __half2 b1 = __floats2half2_rn(y1.x * i1, y1.y * i1);

    hdst[(size_t)r0 * 16 + j] =
        make_uint2(*reinterpret_cast<unsigned int*>(&a0), *reinterpret_cast<unsigned int*>(&b0));
    hdst[(size_t)r1 * 16 + j] =
        make_uint2(*reinterpret_cast<unsigned int*>(&a1), *reinterpret_cast<unsigned int*>(&b1));

    if (layer == 1 || g_needed[r0]) rawz[(size_t)r0 * 16 + j] = make_uint2(0u, 0u);
    if (layer == 1 || g_needed[r1]) rawz[(size_t)r1 * 16 + j] = make_uint2(0u, 0u);
}

// ---------------- scoring ----------------
__device__ __forceinline__ float2 merged_row(int row, int lane) {
    size_t idx = (size_t)row * 32 + lane;

    __half2 h0 = __ldg(&reinterpret_cast<const __half2*>(g_h[0])[idx]);
    __half2 h1 = __ldg(&reinterpret_cast<const __half2*>(g_h[1])[idx]);
    __half2 h2 = __ldg(&reinterpret_cast<const __half2*>(g_h[2])[idx]);
    float2 a3  = __half22float2(__ldg(&reinterpret_cast<const __half2*>(g_rawA)[idx]));

    a3.x = lrelu(a3.x);
    a3.y = lrelu(a3.y);
    float s = warp_sum(a3.x * a3.x + a3.y * a3.y);
    float inv = 1.0f / fmaxf(sqrtf(s), EPS);

    float2 f0 = __half22float2(h0);
    float2 f1 = __half22float2(h1);
    float2 f2 = __half22float2(h2);

    float2 m;
    m.x = f0.x + f1.x + f2.x + a3.x * inv;
    m.y = f0.y + f1.y + f2.y + a3.y * inv;
    return m;
}

__global__ __launch_bounds__(256) void k_score(const int* __restrict__ users,
                                               const int* __restrict__ adj,
                                               const int* __restrict__ weak,
                                               const int* __restrict__ strong,
                                               float* __restrict__ out) {
    int b = blockIdx.x * (blockDim.x >> 5) + (threadIdx.x >> 5);
    if (b >= BATCH) return;
    int lane = threadIdx.x & 31;

    float2 uv = merged_row(users[b], lane);
    float2 m0 = merged_row(NUM_USERS + adj[b], lane);
    float2 m1 = merged_row(NUM_USERS + weak[b], lane);
    float2 m2 = merged_row(NUM_USERS + strong[b], lane);

    float d0 = warp_sum(uv.x * m0.x + uv.y * m0.y);
    float d1 = warp_sum(uv.x * m1.x + uv.y * m1.y);
    float d2 = warp_sum(uv.x * m2.x + uv.y * m2.y);

    if (lane == 0) {
        out[0 * BATCH + b] = 1.0f / (1.0f + expf(-d0 * (1.0f / 16.0f)));
        out[1 * BATCH + b] = 1.0f / (1.0f + expf(-d1 * (1.0f / 16.0f)));
        out[2 * BATCH + b] = 1.0f / (1.0f + expf(-d2 * (1.0f / 16.0f)));
    }
}

extern "C" void kernel_launch(void* const* d_in, const int* in_sizes, int n_in,
                              void* d_out, int out_size) {
    const int*   users  = (const int*)d_in[0];
    const int*   adj    = (const int*)d_in[1];
    const int*   weak   = (const int*)d_in[2];
    const int*   strong = (const int*)d_in[3];
    const int*   erow   = (const int*)d_in[4];
    const int*   ecol   = (const int*)d_in[5];
    const float* eval   = (const float*)d_in[6];
    const float* up     = (const float*)d_in[7];
    const float* ip     = (const float*)d_in[8];
    float* out = (float*)d_out;

    const int ROW4_BLOCKS = (N_NODES + 31) / 32;
    const int SPMM_BLOCKS = ((NNZ / 2) * 8 + 255) / 256;

    // Side stream + events for the independent bitmap/compact branch.
    // Created fresh per call; intentionally not destroyed while stream
    // capture may be active (destroying a capture-participating stream
    // invalidates the capture). kernel_launch runs only a handful of times.
    cudaStream_t s2;
    cudaEvent_t ev_fork, ev_join;
    cudaStreamCreateWithFlags(&s2, cudaStreamNonBlocking);
    cudaEventCreateWithFlags(&ev_fork, cudaEventDisableTiming);
    cudaEventCreateWithFlags(&ev_join, cudaEventDisableTiming);

    // Fork: branch B (bitmap + compaction) runs concurrently with branch A.
    cudaEventRecord(ev_fork, 0);
    cudaStreamWaitEvent(s2, ev_fork, 0);

    // Branch B (side stream): needed-row bitmap -> edge compaction.
    k_zero_needed<<<(N_NODES / 4 + 255) / 256, 256, 0, s2>>>();
    k_mark<<<(BATCH + 255) / 256, 256, 0, s2>>>(users, adj, weak, strong);
    k_compact<<<(NNZ / 4 + 255) / 256, 256, 0, s2>>>(erow, ecol, eval);
    cudaEventRecord(ev_join, s2);

    // Branch A (main stream): init + dense layers 1,2.
    k_init<<<ROW4_BLOCKS, 256>>>(up, ip);
    k_spmm<<<SPMM_BLOCKS, 256>>>(erow, ecol, eval, 1);   // h0 -> rawA
    k_norm<<<ROW4_BLOCKS, 256>>>(1);                     // rawA -> h1, zero rawB
    k_spmm<<<SPMM_BLOCKS, 256>>>(erow, ecol, eval, 2);   // h1 -> rawB

    // Join: norm2 reads g_needed; spmm3c reads the compacted edges.
    cudaStreamWaitEvent(0, ev_join, 0);
    k_norm<<<ROW4_BLOCKS, 256>>>(2);                     // rawB -> h2, zero rawA@needed
    k_spmm3c<<<2048, 256>>>();                           // compacted -> rawA

    k_score<<<(BATCH + 7) / 8, 256>>>(users, adj, weak, strong, out);
}